// round 1
// baseline (speedup 1.0000x reference)
#include <cuda_runtime.h>

#define HH 128
#define WW 128
#define NIMG 2
#define NC 21
#define RR 5

// scratch (no allocations allowed)
__device__ float  g_rgb[NIMG * 3 * HH * WW];   // 2x2-mean-pooled rgb, pre-scaled by 1/sigma_rgb = 10
__device__ float  g_txy[11 * 11];              // exp(-0.5*(dx^2+dy^2)/36)
__device__ double g_acc;

// ---------------------------------------------------------------------------
// Pass 1: downsample+scale rgb, build txy table, zero the accumulator.
// ---------------------------------------------------------------------------
__global__ void prep_kernel(const float* __restrict__ rgb) {
    int idx = blockIdx.x * blockDim.x + threadIdx.x;
    if (blockIdx.x == 0) {
        if (threadIdx.x == 0) g_acc = 0.0;
        if (threadIdx.x < 121) {
            int dy = (int)threadIdx.x / 11 - 5;
            int dx = (int)threadIdx.x % 11 - 5;
            g_txy[threadIdx.x] = __expf(-0.5f * (float)(dx * dx + dy * dy) / 36.0f);
        }
    }
    const int total = NIMG * 3 * HH * WW;
    if (idx < total) {
        int x  = idx % WW;
        int y  = (idx / WW) % HH;
        int nc = idx / (WW * HH);                 // 0..5 (n*3+c)
        const float* p = rgb + (size_t)nc * (2 * HH) * (2 * WW);
        int r0 = 2 * y, c0 = 2 * x, ws = 2 * WW;
        float s = p[r0 * ws + c0] + p[r0 * ws + c0 + 1] +
                  p[(r0 + 1) * ws + c0] + p[(r0 + 1) * ws + c0 + 1];
        g_rgb[idx] = s * (0.25f * 10.0f);
    }
}

// ---------------------------------------------------------------------------
// Pass 2: main CRF kernel. One thread per pixel. Symmetric tap halving:
// iterate only "forward" taps (dy>0, or dy==0 && dx>0), count pairs twice.
// Out-of-bounds taps contribute exp(-0.5*||center feat||^2) in closed form.
// ---------------------------------------------------------------------------
__global__ __launch_bounds__(128) void crf_kernel(const float* __restrict__ Y) {
    const int x = blockIdx.x * 32 + (threadIdx.x & 31);
    const int y = blockIdx.y * 4 + (threadIdx.x >> 5);
    const int n = blockIdx.z;

    const int   PL = HH * WW;                       // plane stride
    const float* yb = Y + (size_t)n * NC * PL + y * WW + x;
    const float* gb = g_rgb + (size_t)n * 3 * PL + y * WW + x;

    float yc[NC];
#pragma unroll
    for (int c = 0; c < NC; c++) yc[c] = __ldg(yb + c * PL);
    const float r0 = __ldg(gb);
    const float g0 = __ldg(gb + PL);
    const float b0 = __ldg(gb + 2 * PL);

    // ---- out-of-bounds taps (zero-padded features): closed form per pixel ----
    int xl = max(x - RR, 0), xr = min(x + RR, WW - 1);
    int yl = max(y - RR, 0), yr = min(y + RR, HH - 1);
    float oobcnt = (float)(121 - (xr - xl + 1) * (yr - yl + 1));
    float epos  = __expf(-0.5f * (float)(x * x + y * y) / 36.0f);
    float ergbc = __expf(-0.5f * (r0 * r0 + g0 * g0 + b0 * b0));

    float term1 = oobcnt * (epos * (0.9f * ergbc + 0.1f));   // Σ kernels (OOB part)
    float term2 = 0.0f;                                       // Σ prod*y

    // ---- dy == 0, dx = 1..R (forward half of the center row) ----
#pragma unroll
    for (int dx = 1; dx <= RR; dx++) {
        if (x + dx < WW) {
            float dr = __ldg(gb + dx) - r0;
            float dg = __ldg(gb + PL + dx) - g0;
            float db = __ldg(gb + 2 * PL + dx) - b0;
            float e  = __expf(-0.5f * (dr * dr + dg * dg + db * db));
            float t  = g_txy[5 * 11 + dx + 5];
            float kern = t * (0.9f * e + 0.1f);
            term1 += 2.0f * kern;
            float dot = 0.0f;
#pragma unroll
            for (int c = 0; c < NC; c++)
                dot = fmaf(yc[c], __ldg(yb + c * PL + dx), dot);
            term2 = fmaf(2.0f * kern, dot, term2);
        }
    }

    // ---- dy = 1..R, dx = -R..R ----
#pragma unroll
    for (int dy = 1; dy <= RR; dy++) {
        if (y + dy < HH) {
#pragma unroll
            for (int dx = -RR; dx <= RR; dx++) {
                int nx = x + dx;
                if ((unsigned)nx < (unsigned)WW) {
                    int off = dy * WW + dx;
                    float dr = __ldg(gb + off) - r0;
                    float dg = __ldg(gb + PL + off) - g0;
                    float db = __ldg(gb + 2 * PL + off) - b0;
                    float e  = __expf(-0.5f * (dr * dr + dg * dg + db * db));
                    float t  = g_txy[(dy + 5) * 11 + dx + 5];
                    float kern = t * (0.9f * e + 0.1f);
                    term1 += 2.0f * kern;
                    float dot = 0.0f;
#pragma unroll
                    for (int c = 0; c < NC; c++)
                        dot = fmaf(yc[c], __ldg(yb + c * PL + off), dot);
                    term2 = fmaf(2.0f * kern, dot, term2);
                }
            }
        }
    }

    // ---- block reduction, atomic into double accumulator ----
    float v = term1 - term2;
#pragma unroll
    for (int s = 16; s > 0; s >>= 1)
        v += __shfl_down_sync(0xFFFFFFFFu, v, s);

    __shared__ float ws[4];
    int lane = threadIdx.x & 31, warp = threadIdx.x >> 5;
    if (lane == 0) ws[warp] = v;
    __syncthreads();
    if (threadIdx.x == 0) {
        float s = ws[0] + ws[1] + ws[2] + ws[3];
        atomicAdd(&g_acc, (double)s);
    }
}

// ---------------------------------------------------------------------------
// Pass 3: finalize scalar.
// ---------------------------------------------------------------------------
__global__ void fin_kernel(float* __restrict__ out) {
    out[0] = (float)(g_acc * (1.0 / (double)(NIMG * HH * WW)));
}

extern "C" void kernel_launch(void* const* d_in, const int* in_sizes, int n_in,
                              void* d_out, int out_size) {
    const float* y   = (const float*)d_in[0];
    const float* rgb = (const float*)d_in[1];
    // defensive: identify inputs by element count
    if (n_in >= 2 && in_sizes[0] == NIMG * 3 * 256 * 256) {
        const float* t = y; y = rgb; rgb = t;
    }

    const int total = NIMG * 3 * HH * WW;
    prep_kernel<<<(total + 255) / 256, 256>>>(rgb);

    dim3 blk(128);
    dim3 grid(WW / 32, HH / 4, NIMG);
    crf_kernel<<<grid, blk>>>(y);

    fin_kernel<<<1, 1>>>((float*)d_out);
}